// round 10
// baseline (speedup 1.0000x reference)
#include <cuda_runtime.h>

// SparseMCFModel — math reduction (validated over 9 passing rounds):
//  * decoder softmax has identical logits within each segment
//    => w[e] = 1/out_degree(edge_row[e]) EXACTLY. GAT/GRU/decoder dead code.
//  * recurrence: x_1 = relu(demands);
//      x_{t+1}[n] = dpos[n] + sum_{e: col(e)=n} w[e]*x_t[row(e)]
//      flow[e]    = w[e] * x_10[row(e)]
//
// Structure: PDL-chained graph, 7 nodes. Updates fused in PAIRS with an
// internal software grid barrier (single-wave grid: 391 blocks x 256 thr
// <= 148 SMs x 8 blocks, so all blocks start; no deadlock). Edges handled
// 2-per-thread via int2/float2. Pre-wait phase touches ONLY harness inputs.

#define NN  20000
#define NE  200000
#define NE2 (NE / 2)              // 100000
#define BS  256
#define GB  ((NE2 + BS - 1) / BS) // 391 blocks (single wave)

__device__ float  d_dpos[NN];
__device__ float  d_x[3][NN];
__device__ int    d_deg[NN];      // zero at replay start (static init / k_final rezero)
__device__ float2 d_w2[NE2];      // per-edge weights, packed 2/thread

// software grid barrier (generation-based; volatile poll)
__device__ unsigned int          g_count = 0;
__device__ volatile unsigned int g_gen   = 0;

__device__ __forceinline__ void pdl_trigger() {
    asm volatile("griddepcontrol.launch_dependents;" ::: "memory");
}
__device__ __forceinline__ void pdl_wait() {
    asm volatile("griddepcontrol.wait;" ::: "memory");
}

__device__ __forceinline__ void grid_sync() {
    __syncthreads();
    if (threadIdx.x == 0) {
        __threadfence();
        unsigned int my = g_gen;
        unsigned int arrived = atomicAdd(&g_count, 1u);
        if (arrived == gridDim.x - 1u) {
            g_count = 0u;
            __threadfence();
            g_gen = my + 1u;
        } else {
            while (g_gen == my) { __nanosleep(32); }
        }
        __threadfence();
    }
    __syncthreads();
}

// node 1: node-init (float2) + degree histogram (int2 rows)
__global__ void __launch_bounds__(BS) k_init_deg(const float* __restrict__ demands,
                                                 const int* __restrict__ row) {
    int i = blockIdx.x * BS + threadIdx.x;
    pdl_trigger();
    if (i < NN / 2) {
        float2 d = __ldg((const float2*)demands + i);
        d.x = d.x > 0.0f ? d.x : 0.0f;
        d.y = d.y > 0.0f ? d.y : 0.0f;
        ((float2*)d_dpos)[i] = d;
        ((float2*)d_x[0])[i] = d;     // x_1
        ((float2*)d_x[1])[i] = d;     // first update target, pre-reset
    }
    if (i < NE2) {
        int2 r = __ldg((const int2*)row + i);
        atomicAdd(&d_deg[r.x], 1);
        atomicAdd(&d_deg[r.y], 1);
    }
}

// node 2: update 1 (x_1 -> x_2) + weight precompute
__global__ void __launch_bounds__(BS) k_upd_first(const int* __restrict__ row,
                                                  const int* __restrict__ col) {
    int i = blockIdx.x * BS + threadIdx.x;
    int2 r = make_int2(0, 0), c = make_int2(0, 0);
    if (i < NE2) { r = __ldg((const int2*)row + i); c = __ldg((const int2*)col + i); }
    pdl_trigger();
    pdl_wait();                       // deg + init complete
    if (i < NE2) {
        float2 w;
        w.x = 1.0f / (float)d_deg[r.x];
        w.y = 1.0f / (float)d_deg[r.y];
        d_w2[i] = w;
        atomicAdd(&d_x[1][c.x], w.x * d_x[0][r.x]);
        atomicAdd(&d_x[1][c.y], w.y * d_x[0][r.y]);
    }
    if (i < NN) d_x[2][i] = d_dpos[i];   // prep buffer for x_3
}

// nodes 3..6: fused PAIR of updates (A then internal grid barrier then B).
// A: read x[cur], atomic x[nxt], reset x[rst]. B: read x[nxt], atomic x[rst], reset x[cur].
__global__ void __launch_bounds__(BS) k_upd_pair(const int* __restrict__ row,
                                                 const int* __restrict__ col,
                                                 int cur, int nxt, int rst) {
    int i = blockIdx.x * BS + threadIdx.x;
    int2 r = make_int2(0, 0), c = make_int2(0, 0);
    if (i < NE2) { r = __ldg((const int2*)row + i); c = __ldg((const int2*)col + i); }
    pdl_trigger();
    pdl_wait();                       // predecessor complete + visible

    float2 w = make_float2(0.f, 0.f);
    if (i < NE2) {
        w = d_w2[i];
        float ax = d_x[cur][r.x];     // batched gathers (MLP)
        float ay = d_x[cur][r.y];
        atomicAdd(&d_x[nxt][c.x], w.x * ax);
        atomicAdd(&d_x[nxt][c.y], w.y * ay);
    }
    if (i < NN) d_x[rst][i] = d_dpos[i];   // B's target, pre-reset

    grid_sync();                      // all atomics of A visible

    if (i < NE2) {
        float bx = d_x[nxt][r.x];
        float by = d_x[nxt][r.y];
        atomicAdd(&d_x[rst][c.x], w.x * bx);
        atomicAdd(&d_x[rst][c.y], w.y * by);
    }
    if (i < NN) d_x[cur][i] = d_dpos[i];   // next kernel's A target, pre-reset
}

// node 7: flow = w * x_10[row]; rezero d_deg for the next replay
__global__ void __launch_bounds__(BS) k_final(const int* __restrict__ row,
                                              float* __restrict__ out, int cur) {
    int i = blockIdx.x * BS + threadIdx.x;
    int2 r = make_int2(0, 0);
    if (i < NE2) r = __ldg((const int2*)row + i);
    pdl_wait();
    if (i < NE2) {
        float2 w = d_w2[i];
        float2 o;
        o.x = w.x * d_x[cur][r.x];
        o.y = w.y * d_x[cur][r.y];
        ((float2*)out)[i] = o;
    }
    if (i < NN) d_deg[i] = 0;
}

static inline void launch_pdl(const void* fn, void** args) {
    cudaLaunchConfig_t cfg = {};
    cfg.gridDim  = dim3(GB);
    cfg.blockDim = dim3(BS);
    cfg.dynamicSmemBytes = 0;
    cfg.stream = 0;
    cudaLaunchAttribute at;
    at.id = cudaLaunchAttributeProgrammaticStreamSerialization;
    at.val.programmaticStreamSerializationAllowed = 1;
    cfg.attrs = &at;
    cfg.numAttrs = 1;
    if (cudaLaunchKernelExC(&cfg, fn, args) != cudaSuccess) {
        cudaGetLastError();
        cfg.numAttrs = 0;             // fallback: serialized launch (wait is benign)
        cudaLaunchKernelExC(&cfg, fn, args);
    }
}

extern "C" void kernel_launch(void* const* d_in, const int* in_sizes, int n_in,
                              void* d_out, int out_size) {
    // Inputs: node_embeddings, demands, edge_row, edge_col, ...
    const float* demands = (const float*)d_in[1];
    const int*   erow    = (const int*)d_in[2];
    const int*   ecol    = (const int*)d_in[3];
    float*       out     = (float*)d_out;

    k_init_deg<<<GB, BS>>>(demands, erow);

    {
        void* args[2] = { (void*)&erow, (void*)&ecol };
        launch_pdl((const void*)k_upd_first, args);
    }

    // updates 2..9 as 4 fused pairs; rotation: pair does (cur,nxt,rst) then (nxt,rst,cur)
    int cur = 1;
    for (int p = 0; p < 4; p++) {
        int nxt = (cur + 1) % 3, rst = (cur + 2) % 3;
        void* args[5] = { (void*)&erow, (void*)&ecol, &cur, &nxt, &rst };
        launch_pdl((const void*)k_upd_pair, args);
        cur = rst;                    // after B: state lives in rst
    }

    {
        // after 1 + 8 updates, x_10 lives in d_x[cur]
        void* args[3] = { (void*)&erow, (void*)&out, &cur };
        launch_pdl((const void*)k_final, args);
    }
}

// round 11
// speedup vs baseline: 1.2390x; 1.2390x over previous
#include <cuda_runtime.h>

// SparseMCFModel — math reduction (validated over 10 passing rounds):
//  * decoder softmax has identical logits within each segment
//    => w[e] = 1/out_degree(edge_row[e]) EXACTLY. GAT/GRU/decoder dead code.
//  * recurrence: x_1 = relu(demands);
//      x_{t+1}[n] = dpos[n] + sum_{e: col(e)=n} w[e]*x_t[row(e)]
//      flow[e]    = w[e] * x_10[row(e)]
//
// Structure lessons (R2..R10): software grid barriers & persistent kernels
// lose; edge sorting loses; PDL-chained multi-launch graph wins (R9=41.1us).
// This round: R9 skeleton exactly, BS 256->128 (1564 blocks) to raise
// occupancy 52%->~66% — the updates are latency-bound, busy-time ~1.5us of
// the 3.2us wall, so more resident warps hide the exposed L2 latency.

#define NN 20000
#define NE 200000
#define BS 128
#define GE ((NE + BS - 1) / BS)   // 1564 blocks; covers NN too

__device__ float d_dpos[NN];
__device__ float d_x[3][NN];
__device__ int   d_deg[NN];   // zero at replay start (static init / k_final rezero)
__device__ float d_w[NE];     // per-edge weight, edge order

__device__ __forceinline__ void pdl_trigger() {
    asm volatile("griddepcontrol.launch_dependents;" ::: "memory");
}
__device__ __forceinline__ void pdl_wait() {
    asm volatile("griddepcontrol.wait;" ::: "memory");
}

// node 1: fused node-init + degree histogram
__global__ void __launch_bounds__(BS) k_init_deg(const float* __restrict__ demands,
                                                 const int* __restrict__ row) {
    int i = blockIdx.x * BS + threadIdx.x;
    pdl_trigger();
    if (i < NN / 2) {
        float2 d = __ldg((const float2*)demands + i);
        d.x = d.x > 0.0f ? d.x : 0.0f;
        d.y = d.y > 0.0f ? d.y : 0.0f;
        ((float2*)d_dpos)[i] = d;
        ((float2*)d_x[0])[i] = d;     // x_1
        ((float2*)d_x[1])[i] = d;     // first update target, pre-reset
    }
    if (i < NE) atomicAdd(&d_deg[__ldg(&row[i])], 1);
}

// node 2: first update (x_1 -> x_2) + weight precompute
__global__ void __launch_bounds__(BS) k_upd_first(const int* __restrict__ row,
                                                  const int* __restrict__ col) {
    int i = blockIdx.x * BS + threadIdx.x;
    int r = 0, c = 0;
    if (i < NE) { r = __ldg(&row[i]); c = __ldg(&col[i]); }   // pure inputs, pre-wait
    pdl_trigger();
    pdl_wait();                          // deg + init complete + visible
    if (i < NE) {
        float w = 1.0f / (float)d_deg[r];
        d_w[i] = w;
        atomicAdd(&d_x[1][c], w * d_x[0][r]);   // fire-and-forget RED
    }
    if (i < NN) d_x[2][i] = d_dpos[i];          // prep buffer for x_3
}

// nodes 3..10: generic updates (3-buffer rotation)
__global__ void __launch_bounds__(BS) k_update(const int* __restrict__ row,
                                               const int* __restrict__ col,
                                               int cur, int nxt, int rst) {
    int i = blockIdx.x * BS + threadIdx.x;
    int r = 0, c = 0;
    if (i < NE) { r = __ldg(&row[i]); c = __ldg(&col[i]); }   // pure inputs, pre-wait
    pdl_trigger();
    pdl_wait();                          // prior update complete + visible
    if (i < NE) {
        float xv = d_x[cur][r];          // ONE random gather
        atomicAdd(&d_x[nxt][c], d_w[i] * xv);
    }
    if (i < NN) d_x[rst][i] = d_dpos[i];
}

// node 11: flow = w * x_10[row]; rezero d_deg for the next replay
__global__ void __launch_bounds__(BS) k_final(const int* __restrict__ row,
                                              float* __restrict__ out, int cur) {
    int e = blockIdx.x * BS + threadIdx.x;
    int r = 0;
    if (e < NE) r = __ldg(&row[e]);
    pdl_wait();
    if (e < NE) out[e] = d_w[e] * d_x[cur][r];
    if (e < NN) d_deg[e] = 0;
}

static inline void launch_pdl(const void* fn, void** args) {
    cudaLaunchConfig_t cfg = {};
    cfg.gridDim  = dim3(GE);
    cfg.blockDim = dim3(BS);
    cfg.dynamicSmemBytes = 0;
    cfg.stream = 0;
    cudaLaunchAttribute at;
    at.id = cudaLaunchAttributeProgrammaticStreamSerialization;
    at.val.programmaticStreamSerializationAllowed = 1;
    cfg.attrs = &at;
    cfg.numAttrs = 1;
    if (cudaLaunchKernelExC(&cfg, fn, args) != cudaSuccess) {
        cudaGetLastError();
        cfg.numAttrs = 0;                // fallback: serialized launch (wait is benign)
        cudaLaunchKernelExC(&cfg, fn, args);
    }
}

extern "C" void kernel_launch(void* const* d_in, const int* in_sizes, int n_in,
                              void* d_out, int out_size) {
    // Inputs: node_embeddings, demands, edge_row, edge_col, W_gat, a_src,
    //         a_dst, Wx, Wh, b_gru, Wd, bd
    const float* demands = (const float*)d_in[1];
    const int*   erow    = (const int*)d_in[2];
    const int*   ecol    = (const int*)d_in[3];
    float*       out     = (float*)d_out;

    k_init_deg<<<GE, BS>>>(demands, erow);

    {
        void* args[2] = { (void*)&erow, (void*)&ecol };
        launch_pdl((const void*)k_upd_first, args);
    }

    int cur = 1;
    for (int t = 0; t < 8; t++) {
        int nxt = (cur + 1) % 3, rst = (cur + 2) % 3;
        void* args[5] = { (void*)&erow, (void*)&ecol, &cur, &nxt, &rst };
        launch_pdl((const void*)k_update, args);
        cur = nxt;
    }

    {
        void* args[3] = { (void*)&erow, (void*)&out, &cur };
        launch_pdl((const void*)k_final, args);
    }
}

// round 12
// speedup vs baseline: 1.2496x; 1.0086x over previous
#include <cuda_runtime.h>

// SparseMCFModel — math reduction (validated over 11 passing rounds):
//  * decoder softmax has identical logits within each segment
//    => w[e] = 1/out_degree(edge_row[e]) EXACTLY. GAT/GRU/decoder dead code.
//  * recurrence: x_1 = relu(demands);
//      x_{t+1}[n] = dpos[n] + sum_{e: col(e)=n} w[e]*x_t[row(e)]
//      flow[e]    = w[e] * x_10[row(e)]
//
// Structure: PDL-chained 11-node graph (R9 skeleton, best=41.1us).
// This round: minimize the POST-pdl_wait critical path.
//  - 4-buffer rotation: step t reads x[(t-1)%4], writes x[t%4], resets
//    x[(t+1)%4]. The reset buffer is untouched by steps t-1 and t
//    (last toucher = step t-2, fully complete) => reset moves PRE-wait.
//  - d_w immutable after k_upd_first => updates 3..9 and k_final load it
//    PRE-wait; only the first generic update loads it post-wait (flag).
//  - d_deg rezero moves pre-wait in k_final (no predecessor touches deg).
// Post-wait per update = ONE random gather + ONE fire-and-forget RED.

#define NN 20000
#define NE 200000
#define BS 256
#define GE ((NE + BS - 1) / BS)   // 782 blocks; covers NN too

__device__ float d_dpos[NN];
__device__ float d_x[4][NN];
__device__ int   d_deg[NN];   // zero at replay start (static init / k_final rezero)
__device__ float d_w[NE];     // per-edge weight, edge order (written by k_upd_first only)

__device__ __forceinline__ void pdl_trigger() {
    asm volatile("griddepcontrol.launch_dependents;" ::: "memory");
}
__device__ __forceinline__ void pdl_wait() {
    asm volatile("griddepcontrol.wait;" ::: "memory");
}

// node 1: fused node-init + degree histogram
// step 1 (k_upd_first) reads x[0], writes x[1]; init both to dpos.
__global__ void __launch_bounds__(BS) k_init_deg(const float* __restrict__ demands,
                                                 const int* __restrict__ row) {
    int i = blockIdx.x * BS + threadIdx.x;
    pdl_trigger();
    if (i < NN / 2) {
        float2 d = __ldg((const float2*)demands + i);
        d.x = d.x > 0.0f ? d.x : 0.0f;
        d.y = d.y > 0.0f ? d.y : 0.0f;
        ((float2*)d_dpos)[i] = d;
        ((float2*)d_x[0])[i] = d;     // x_1 (read buffer of step 1)
        ((float2*)d_x[1])[i] = d;     // write target of step 1, pre-reset
    }
    if (i < NE) atomicAdd(&d_deg[__ldg(&row[i])], 1);
}

// node 2 (step 1): x_1 -> x_2, weight precompute; pre-wait resets x[2].
__global__ void __launch_bounds__(BS) k_upd_first(const int* __restrict__ row,
                                                  const int* __restrict__ col) {
    int i = blockIdx.x * BS + threadIdx.x;
    int r = 0, c = 0;
    if (i < NE) { r = __ldg(&row[i]); c = __ldg(&col[i]); }   // pure inputs
    if (i < NN) d_x[2][i] = d_dpos[i];    // pre-wait reset (init doesn't touch x[2])
    pdl_trigger();
    pdl_wait();                           // deg + init complete + visible
    if (i < NE) {
        float w = 1.0f / (float)d_deg[r];
        d_w[i] = w;
        atomicAdd(&d_x[1][c], w * d_x[0][r]);   // fire-and-forget RED
    }
}

// nodes 3..10 (steps 2..9): 4-buffer rotation.
// wpost=1 only for step 2 (predecessor k_upd_first still writing d_w).
__global__ void __launch_bounds__(BS) k_update(const int* __restrict__ row,
                                               const int* __restrict__ col,
                                               int cur, int nxt, int rst, int wpost) {
    int i = blockIdx.x * BS + threadIdx.x;
    int r = 0, c = 0;
    float w = 0.0f;
    if (i < NE) {
        r = __ldg(&row[i]); c = __ldg(&col[i]);               // pure inputs
        if (!wpost) w = d_w[i];                               // immutable: pre-wait OK
    }
    if (i < NN) d_x[rst][i] = d_dpos[i];  // pre-wait reset (untouched by t-1 / t)
    pdl_trigger();
    pdl_wait();                           // prior step complete + visible
    if (i < NE) {
        if (wpost) w = d_w[i];
        float xv = __ldg(&d_x[cur][r]);   // ONE random gather (post-wait)
        atomicAdd(&d_x[nxt][c], w * xv);  // ONE fire-and-forget RED
    }
}

// node 11: flow = w * x_10[row]; pre-wait: w load + deg rezero.
__global__ void __launch_bounds__(BS) k_final(const int* __restrict__ row,
                                              float* __restrict__ out, int cur) {
    int e = blockIdx.x * BS + threadIdx.x;
    int r = 0; float w = 0.0f;
    if (e < NE) { r = __ldg(&row[e]); w = d_w[e]; }           // w immutable here
    if (e < NN) d_deg[e] = 0;             // pre-wait: no predecessor touches deg
    pdl_wait();
    if (e < NE) out[e] = w * __ldg(&d_x[cur][r]);
}

static inline void launch_pdl(const void* fn, void** args) {
    cudaLaunchConfig_t cfg = {};
    cfg.gridDim  = dim3(GE);
    cfg.blockDim = dim3(BS);
    cfg.dynamicSmemBytes = 0;
    cfg.stream = 0;
    cudaLaunchAttribute at;
    at.id = cudaLaunchAttributeProgrammaticStreamSerialization;
    at.val.programmaticStreamSerializationAllowed = 1;
    cfg.attrs = &at;
    cfg.numAttrs = 1;
    if (cudaLaunchKernelExC(&cfg, fn, args) != cudaSuccess) {
        cudaGetLastError();
        cfg.numAttrs = 0;                 // fallback: serialized launch (wait is benign)
        cudaLaunchKernelExC(&cfg, fn, args);
    }
}

extern "C" void kernel_launch(void* const* d_in, const int* in_sizes, int n_in,
                              void* d_out, int out_size) {
    // Inputs: node_embeddings, demands, edge_row, edge_col, W_gat, a_src,
    //         a_dst, Wx, Wh, b_gru, Wd, bd
    const float* demands = (const float*)d_in[1];
    const int*   erow    = (const int*)d_in[2];
    const int*   ecol    = (const int*)d_in[3];
    float*       out     = (float*)d_out;

    k_init_deg<<<GE, BS>>>(demands, erow);

    {
        void* args[2] = { (void*)&erow, (void*)&ecol };
        launch_pdl((const void*)k_upd_first, args);
    }

    // steps 2..9: read x[(t-1)%4], write x[t%4], reset x[(t+1)%4]
    for (int t = 2; t <= 9; t++) {
        int cur = (t - 1) & 3, nxt = t & 3, rst = (t + 1) & 3;
        int wpost = (t == 2) ? 1 : 0;
        void* args[6] = { (void*)&erow, (void*)&ecol, &cur, &nxt, &rst, &wpost };
        launch_pdl((const void*)k_update, args);
    }

    {
        int cur = 9 & 3;   // x_10 lives in d_x[1]
        void* args[3] = { (void*)&erow, (void*)&out, &cur };
        launch_pdl((const void*)k_final, args);
    }
}